// round 13
// baseline (speedup 1.0000x reference)
#include <cuda_runtime.h>
#include <math.h>

#define BB 32
#define AA 5
#define CC 80
#define HH 52
#define WW 52
#define NBOX 50
#define HW (HH * WW)          // 2704
#define NCELL_PER_B (AA * HW) // 13520
#define CH (CC + 5)           // 85
#define BLK 256
#define CPT 2
#define CELLS_PER_BLK (BLK * CPT)                 // 512
#define HOT_BLOCKS_PER_B ((NCELL_PER_B + CELLS_PER_BLK - 1) / CELLS_PER_BLK)  // 27
#define SCAT_SPLIT 4
#define SCAT_BLOCKS (BB * SCAT_SPLIT)             // 128
#define TOTAL_BLOCKS (SCAT_BLOCKS + BB * HOT_BLOCKS_PER_B) // 128 + 864 = 992

__constant__ float c_aw[AA] = {1.3221f, 3.19275f, 5.05587f, 9.47112f, 11.2364f};
__constant__ float c_ah[AA] = {1.73145f, 4.00944f, 8.09892f, 4.84053f, 10.0071f};

static __device__ __forceinline__ float sigmoidf_(float x) {
    return 1.0f / (1.0f + __expf(-x));
}

static __device__ __forceinline__ float warpReduceSum(float v) {
    #pragma unroll
    for (int o = 16; o > 0; o >>= 1) v += __shfl_xor_sync(0xffffffffu, v, o);
    return v;
}
static __device__ __forceinline__ float warpReduceMax(float v) {
    #pragma unroll
    for (int o = 16; o > 0; o >>= 1) v = fmaxf(v, __shfl_xor_sync(0xffffffffu, v, o));
    return v;
}

// ---------------------------------------------------------------------------
// ONE kernel, two block roles (independent; overlap on the SM array):
//   blocks [0, SCAT_BLOCKS)   : scatter + dedup + correction; 4 blocks/batch
//   blocks [SCAT_BLOCKS, ...) : default-target loss; each thread owns TWO
//       COLUMN-ADJACENT cells (same row, same anchor) -> warp-uniform y-overlap
//       allows __any_sync skip of the x-side for ~60% of boxes. Skipped terms
//       contribute (-a375 < 0 < t0) to the running max -> decision unchanged.
// ---------------------------------------------------------------------------
__global__ __launch_bounds__(BLK) void region_loss_kernel(
    const float* __restrict__ pred, const float* __restrict__ target,
    float* __restrict__ out)
{
    __shared__ float4 s_box[NBOX];    // (x1, y1, x2, y2)
    __shared__ float  s_a375[NBOX];   // 0.375 * garea
    __shared__ int    s_cell[NBOX];
    __shared__ float4 s_tbox[NBOX];
    __shared__ float  s_iou[NBOX];
    __shared__ int    s_cls[NBOX];
    __shared__ int    s_win[NBOX];
    __shared__ float  s_red[BLK / 32];

    const int tid  = threadIdx.x;
    const int lane = tid & 31;
    const int warp = tid >> 5;

    if (blockIdx.x < SCAT_BLOCKS) {
        // =================== ROLE A: scatter + correction ===================
        const int b   = blockIdx.x / SCAT_SPLIT;
        const int sub = blockIdx.x % SCAT_SPLIT;

        // ---- Phase 1: build records + gt corner table (threads 0..49) ----
        if (tid < NBOX) {
            const float* t = target + (size_t)(b * NBOX + tid) * 5;
            const float rawx = t[1];
            if (rawx > 0.0f) {
                const float gx = rawx * WW, gy = t[2] * HH;
                const float gw = t[3] * WW, gh = t[4] * HH;

                s_box[tid]  = make_float4(gx - 0.5f * gw, gy - 0.5f * gh,
                                          gx + 0.5f * gw, gy + 0.5f * gh);
                s_a375[tid] = 0.375f * (gw * gh);

                int   ba   = 0;
                float best = -1.0f;
                #pragma unroll
                for (int a = 0; a < AA; a++) {
                    float inter = fminf(gw, c_aw[a]) * fminf(gh, c_ah[a]);
                    float uni   = gw * gh + c_aw[a] * c_ah[a] - inter;
                    float rr    = inter / uni;
                    if (rr > best) { best = rr; ba = a; }
                }

                int gi = (int)gx; gi = gi < 0 ? 0 : (gi > WW - 1 ? WW - 1 : gi);
                int gj = (int)gy; gj = gj < 0 ? 0 : (gj > HH - 1 ? HH - 1 : gj);

                const float* pb = pred + ((size_t)(b * AA + ba) * CH) * HW + gj * WW + gi;
                const float bx = sigmoidf_(pb[0]) + (float)gi;
                const float by = sigmoidf_(pb[HW]) + (float)gj;
                const float bw = __expf(pb[2 * HW]) * c_aw[ba];
                const float bh = __expf(pb[3 * HW]) * c_ah[ba];

                const float iw = fmaxf(fminf(gx + 0.5f * gw, bx + 0.5f * bw) -
                                       fmaxf(gx - 0.5f * gw, bx - 0.5f * bw), 0.0f);
                const float ih = fmaxf(fminf(gy + 0.5f * gh, by + 0.5f * bh) -
                                       fmaxf(gy - 0.5f * gh, by - 0.5f * bh), 0.0f);
                const float inter = iw * ih;
                const float uni   = gw * gh + bw * bh - inter;

                s_cell[tid] = ba * HW + gj * WW + gi;
                s_tbox[tid] = make_float4(gx - (float)gi, gy - (float)gj,
                                          __logf(gw / c_aw[ba]), __logf(gh / c_ah[ba]));
                s_iou[tid]  = inter / uni;
                int tc = (int)t[0]; tc = tc < 0 ? 0 : (tc > CC - 1 ? CC - 1 : tc);
                s_cls[tid]  = tc;
            } else {
                s_cell[tid] = -1;
                s_box[tid]  = make_float4(1e30f, 1e30f, -1e30f, -1e30f);
                s_a375[tid] = 1e30f;
            }
        }
        __syncthreads();

        // ---- Phase 2: parallel last-writer-wins dedup ----
        if (tid < NBOX) {
            const int mycell = s_cell[tid];
            bool win = (mycell >= 0);
            if (win) {
                for (int j = tid + 1; j < NBOX; j++) win &= (s_cell[j] != mycell);
            }
            s_win[tid] = win ? 1 : 0;
        }
        __syncthreads();

        // ---- Phase 3: correction; records split by rid % SCAT_SPLIT ----
        float acc = 0.0f;
        for (int rid = sub + SCAT_SPLIT * warp; rid < NBOX;
             rid += SCAT_SPLIT * (BLK / 32)) {
            if (!s_win[rid]) continue;

            const int cell = s_cell[rid];
            const int a  = cell / HW;
            const int r  = cell % HW;

            const float* pb = pred + ((size_t)(b * AA + a) * CH) * HW + r;
            const float q2 = pb[2 * HW], q3 = pb[3 * HW];
            const float sx = sigmoidf_(pb[0]), sy = sigmoidf_(pb[HW]);
            const float cf = sigmoidf_(pb[4 * HW]);
            const float bw = __expf(q2) * c_aw[a], bh = __expf(q3) * c_ah[a];
            const float bx = sx + (float)(r % WW), by = sy + (float)(r / WW);

            const float px1 = bx - 0.5f * bw, px2 = bx + 0.5f * bw;
            const float py1 = by - 0.5f * bh, py2 = by + 0.5f * bh;
            const float t0  = 0.375f * (bw * bh);

            // silence test (same take-path arithmetic as hot role)
            float m = -1e30f;
            for (int n = lane; n < NBOX; n += 32) {
                const float4 g = s_box[n];
                float iw = fminf(px2, g.z) - fmaxf(px1, g.x);
                float ih = fminf(py2, g.w) - fmaxf(py1, g.y);
                m = fmaxf(m, __fmaf_rn(fmaxf(iw, 0.0f), fmaxf(ih, 0.0f), -s_a375[n]));
            }
            m = warpReduceMax(m);
            const float mask_def = (m > t0) ? 0.0f : 1.0f;

            const float dx0 = sx - 0.5f, dy0 = sy - 0.5f;
            const float v_def = 0.5f * (dx0 * dx0 + dy0 * dy0 + q2 * q2 + q3 * q3 +
                                        cf * cf * mask_def);

            const float4 tb   = s_tbox[rid];
            const float  tcnf = s_iou[rid];
            const int    tc   = s_cls[rid];

            // 80-way log-softmax CE, lanes stride classes
            const float* cl = pb + 5 * HW;
            float mx = -1e30f;
            for (int c = lane; c < CC; c += 32) mx = fmaxf(mx, cl[c * HW]);
            mx = warpReduceMax(mx);
            float s = 0.0f;
            for (int c = lane; c < CC; c += 32) s += __expf(cl[c * HW] - mx);
            s = warpReduceSum(s);
            const float ce = mx + __logf(s) - cl[tc * HW];

            const float dx = sx - tb.x, dy = sy - tb.y;
            const float dw = q2 - tb.z, dh = q3 - tb.w;
            const float dc = cf - tcnf;
            const float v_true = 0.5f * (dx * dx + dy * dy + dw * dw + dh * dh +
                                         dc * dc * 5.0f) + ce;

            if (lane == 0) acc += v_true - v_def;
        }

        float wv = warpReduceSum(acc);
        if (lane == 0) s_red[warp] = wv;
        __syncthreads();
        if (warp == 0) {
            float bv = (lane < (BLK / 32)) ? s_red[lane] : 0.0f;
            bv = warpReduceSum(bv);
            if (lane == 0) atomicAdd(out, bv);
        }
        return;
    }

    // ===================== ROLE B: default-target loss =====================
    const int gid   = blockIdx.x - SCAT_BLOCKS;
    const int b     = gid / HOT_BLOCKS_PER_B;
    const int chunk = gid % HOT_BLOCKS_PER_B;

    if (tid < NBOX) {
        const float* t = target + (size_t)(b * NBOX + tid) * 5;
        float x = t[1] * WW, y = t[2] * HH, w = t[3] * WW, h = t[4] * HH;
        if (t[1] > 0.0f) {
            s_box[tid]  = make_float4(x - 0.5f * w, y - 0.5f * h,
                                      x + 0.5f * w, y + 0.5f * h);
            s_a375[tid] = 0.375f * (w * h);
        } else {
            s_box[tid]  = make_float4(1e30f, 1e30f, -1e30f, -1e30f);
            s_a375[tid] = 1e30f;
        }
    }
    __syncthreads();

    // two COLUMN-ADJACENT cells per thread: ci0 = even, ci1 = ci0+1.
    // NCELL_PER_B is even -> ok0 == ok1. Pairs never cross a row (WW even)
    // or an anchor plane (HW even).
    const int pi   = chunk * CELLS_PER_BLK + 2 * tid;
    const bool ok  = (pi + 1) < NCELL_PER_B;
    const int ci0  = ok ? pi : 0;

    const int a0 = ci0 / HW, r0 = ci0 % HW;
    const int col0 = r0 % WW;
    const int row0 = r0 / WW;

    const float* pb = pred + ((size_t)(b * AA + a0) * CH) * HW + r0;
    // vectorized loads: r0 even, HW even -> 8B aligned
    const float2 v0 = *(const float2*)(pb);
    const float2 v1 = *(const float2*)(pb + HW);
    const float2 v2 = *(const float2*)(pb + 2 * HW);
    const float2 v3 = *(const float2*)(pb + 3 * HW);
    const float2 v4 = *(const float2*)(pb + 4 * HW);

    const float sx0 = sigmoidf_(v0.x), sx1 = sigmoidf_(v0.y);
    const float sy0 = sigmoidf_(v1.x), sy1 = sigmoidf_(v1.y);
    const float cf0 = sigmoidf_(v4.x), cf1 = sigmoidf_(v4.y);

    const float bw0 = __expf(v2.x) * c_aw[a0], bh0 = __expf(v3.x) * c_ah[a0];
    const float bw1 = __expf(v2.y) * c_aw[a0], bh1 = __expf(v3.y) * c_ah[a0];

    const float bx0 = sx0 + (float)col0;
    const float bx1 = sx1 + (float)(col0 + 1);
    const float by0 = sy0 + (float)row0;
    const float by1 = sy1 + (float)row0;

    const float px1_0 = bx0 - 0.5f * bw0, px2_0 = bx0 + 0.5f * bw0;
    const float py1_0 = by0 - 0.5f * bh0, py2_0 = by0 + 0.5f * bh0;
    const float px1_1 = bx1 - 0.5f * bw1, px2_1 = bx1 + 0.5f * bw1;
    const float py1_1 = by1 - 0.5f * bh1, py2_1 = by1 + 0.5f * bh1;
    const float t0_0 = 0.375f * (bw0 * bh0);
    const float t0_1 = 0.375f * (bw1 * bh1);

    float m0 = -1e30f, m1 = -1e30f;
    #pragma unroll 10
    for (int n = 0; n < NBOX; n++) {
        const float4 g = s_box[n];     // (x1, y1, x2, y2)

        // y-overlap first: x-independent, nearly warp-uniform (same rows)
        const float ih0 = fminf(py2_0, g.w) - fmaxf(py1_0, g.y);
        const float ih1 = fminf(py2_1, g.w) - fmaxf(py1_1, g.y);

        if (__any_sync(0xffffffffu, fmaxf(ih0, ih1) > 0.0f)) {
            const float an = s_a375[n];
            float iw0 = fminf(px2_0, g.z) - fmaxf(px1_0, g.x);
            m0 = fmaxf(m0, __fmaf_rn(fmaxf(iw0, 0.0f), fmaxf(ih0, 0.0f), -an));
            float iw1 = fminf(px2_1, g.z) - fmaxf(px1_1, g.x);
            m1 = fmaxf(m1, __fmaf_rn(fmaxf(iw1, 0.0f), fmaxf(ih1, 0.0f), -an));
        }
        // skipped terms are (0*iw - an) = -an < 0 < t0 -> decision unchanged
    }

    float v = 0.0f;
    if (ok) {
        const float mk0 = (m0 > t0_0) ? 0.0f : 1.0f;
        const float mk1 = (m1 > t0_1) ? 0.0f : 1.0f;
        const float dx0 = sx0 - 0.5f, dy0 = sy0 - 0.5f;
        const float dx1 = sx1 - 0.5f, dy1 = sy1 - 0.5f;
        v += 0.5f * (dx0 * dx0 + dy0 * dy0 + v2.x * v2.x + v3.x * v3.x +
                     cf0 * cf0 * mk0);
        v += 0.5f * (dx1 * dx1 + dy1 * dy1 + v2.y * v2.y + v3.y * v3.y +
                     cf1 * cf1 * mk1);
    }

    float wv = warpReduceSum(v);
    if (lane == 0) s_red[warp] = wv;
    __syncthreads();
    if (warp == 0) {
        float bv = (lane < (BLK / 32)) ? s_red[lane] : 0.0f;
        bv = warpReduceSum(bv);
        if (lane == 0) atomicAdd(out, bv);
    }
}

extern "C" void kernel_launch(void* const* d_in, const int* in_sizes, int n_in,
                              void* d_out, int out_size)
{
    const float* pred   = (const float*)d_in[0];
    const float* target = (const float*)d_in[1];
    float* out = (float*)d_out;

    cudaMemsetAsync(out, 0, (size_t)out_size * sizeof(float));
    region_loss_kernel<<<TOTAL_BLOCKS, BLK>>>(pred, target, out);
}

// round 14
// speedup vs baseline: 1.1125x; 1.1125x over previous
#include <cuda_runtime.h>
#include <math.h>

#define BB 32
#define AA 5
#define CC 80
#define HH 52
#define WW 52
#define NBOX 50
#define HW (HH * WW)          // 2704
#define NCELL_PER_B (AA * HW) // 13520
#define CH (CC + 5)           // 85
#define BLK 256
#define CPT 2
#define CELLS_PER_BLK (BLK * CPT)                 // 512
#define HOT_BLOCKS_PER_B ((NCELL_PER_B + CELLS_PER_BLK - 1) / CELLS_PER_BLK)  // 27
#define SCAT_SPLIT 4
#define SCAT_BLOCKS (BB * SCAT_SPLIT)             // 128
#define TOTAL_BLOCKS (SCAT_BLOCKS + BB * HOT_BLOCKS_PER_B) // 128 + 864 = 992

__constant__ float c_aw[AA] = {1.3221f, 3.19275f, 5.05587f, 9.47112f, 11.2364f};
__constant__ float c_ah[AA] = {1.73145f, 4.00944f, 8.09892f, 4.84053f, 10.0071f};

static __device__ __forceinline__ float sigmoidf_(float x) {
    return 1.0f / (1.0f + __expf(-x));
}

static __device__ __forceinline__ float warpReduceSum(float v) {
    #pragma unroll
    for (int o = 16; o > 0; o >>= 1) v += __shfl_xor_sync(0xffffffffu, v, o);
    return v;
}
static __device__ __forceinline__ float warpReduceMax(float v) {
    #pragma unroll
    for (int o = 16; o > 0; o >>= 1) v = fmaxf(v, __shfl_xor_sync(0xffffffffu, v, o));
    return v;
}

// Silence-test term: decides (inter > 0.375*(parea+garea)) identically with
// ONE clamp: if iw<=0 -> -an < 0 < t0; if iw>0, ih<=0 -> <= -an < 0;
// both positive -> exact intersection term.
static __device__ __forceinline__ float sil_term(float iw, float ih, float an) {
    return __fmaf_rn(fmaxf(iw, 0.0f), ih, -an);
}

// ---------------------------------------------------------------------------
// ONE kernel, two block roles (independent; overlap on the SM array):
//   blocks [0, SCAT_BLOCKS)   : scatter + dedup + correction; 4 blocks/batch
//   blocks [SCAT_BLOCKS, ...) : default-target loss; each thread owns two
//                               column-adjacent cells (float2 loads, CPT=2)
// Both roles end in one atomicAdd(out) per block.
// ---------------------------------------------------------------------------
__global__ __launch_bounds__(BLK) void region_loss_kernel(
    const float* __restrict__ pred, const float* __restrict__ target,
    float* __restrict__ out)
{
    __shared__ float4 s_box[NBOX];    // (x1, y1, x2, y2)
    __shared__ float  s_a375[NBOX];   // 0.375 * garea
    __shared__ int    s_cell[NBOX];
    __shared__ float4 s_tbox[NBOX];
    __shared__ float  s_iou[NBOX];
    __shared__ int    s_cls[NBOX];
    __shared__ int    s_win[NBOX];
    __shared__ float  s_red[BLK / 32];

    const int tid  = threadIdx.x;
    const int lane = tid & 31;
    const int warp = tid >> 5;

    if (blockIdx.x < SCAT_BLOCKS) {
        // =================== ROLE A: scatter + correction ===================
        const int b   = blockIdx.x / SCAT_SPLIT;
        const int sub = blockIdx.x % SCAT_SPLIT;

        // ---- Phase 1: build records + gt corner table (threads 0..49) ----
        if (tid < NBOX) {
            const float* t = target + (size_t)(b * NBOX + tid) * 5;
            const float rawx = t[1];
            if (rawx > 0.0f) {
                const float gx = rawx * WW, gy = t[2] * HH;
                const float gw = t[3] * WW, gh = t[4] * HH;

                s_box[tid]  = make_float4(gx - 0.5f * gw, gy - 0.5f * gh,
                                          gx + 0.5f * gw, gy + 0.5f * gh);
                s_a375[tid] = 0.375f * (gw * gh);

                int   ba   = 0;
                float best = -1.0f;
                #pragma unroll
                for (int a = 0; a < AA; a++) {
                    float inter = fminf(gw, c_aw[a]) * fminf(gh, c_ah[a]);
                    float uni   = gw * gh + c_aw[a] * c_ah[a] - inter;
                    float rr    = inter / uni;
                    if (rr > best) { best = rr; ba = a; }
                }

                int gi = (int)gx; gi = gi < 0 ? 0 : (gi > WW - 1 ? WW - 1 : gi);
                int gj = (int)gy; gj = gj < 0 ? 0 : (gj > HH - 1 ? HH - 1 : gj);

                const float* pb = pred + ((size_t)(b * AA + ba) * CH) * HW + gj * WW + gi;
                const float bx = sigmoidf_(pb[0]) + (float)gi;
                const float by = sigmoidf_(pb[HW]) + (float)gj;
                const float bw = __expf(pb[2 * HW]) * c_aw[ba];
                const float bh = __expf(pb[3 * HW]) * c_ah[ba];

                const float iw = fmaxf(fminf(gx + 0.5f * gw, bx + 0.5f * bw) -
                                       fmaxf(gx - 0.5f * gw, bx - 0.5f * bw), 0.0f);
                const float ih = fmaxf(fminf(gy + 0.5f * gh, by + 0.5f * bh) -
                                       fmaxf(gy - 0.5f * gh, by - 0.5f * bh), 0.0f);
                const float inter = iw * ih;
                const float uni   = gw * gh + bw * bh - inter;

                s_cell[tid] = ba * HW + gj * WW + gi;
                s_tbox[tid] = make_float4(gx - (float)gi, gy - (float)gj,
                                          __logf(gw / c_aw[ba]), __logf(gh / c_ah[ba]));
                s_iou[tid]  = inter / uni;
                int tc = (int)t[0]; tc = tc < 0 ? 0 : (tc > CC - 1 ? CC - 1 : tc);
                s_cls[tid]  = tc;
            } else {
                s_cell[tid] = -1;
                s_box[tid]  = make_float4(1e30f, 1e30f, -1e30f, -1e30f);
                s_a375[tid] = 1e30f;
            }
        }
        __syncthreads();

        // ---- Phase 2: parallel last-writer-wins dedup ----
        if (tid < NBOX) {
            const int mycell = s_cell[tid];
            bool win = (mycell >= 0);
            if (win) {
                for (int j = tid + 1; j < NBOX; j++) win &= (s_cell[j] != mycell);
            }
            s_win[tid] = win ? 1 : 0;
        }
        __syncthreads();

        // ---- Phase 3: correction; records split by rid % SCAT_SPLIT ----
        float acc = 0.0f;
        for (int rid = sub + SCAT_SPLIT * warp; rid < NBOX;
             rid += SCAT_SPLIT * (BLK / 32)) {
            if (!s_win[rid]) continue;

            const int cell = s_cell[rid];
            const int a  = cell / HW;
            const int r  = cell % HW;

            const float* pb = pred + ((size_t)(b * AA + a) * CH) * HW + r;
            const float q2 = pb[2 * HW], q3 = pb[3 * HW];
            const float sx = sigmoidf_(pb[0]), sy = sigmoidf_(pb[HW]);
            const float cf = sigmoidf_(pb[4 * HW]);
            const float bw = __expf(q2) * c_aw[a], bh = __expf(q3) * c_ah[a];
            const float bx = sx + (float)(r % WW), by = sy + (float)(r / WW);

            const float px1 = bx - 0.5f * bw, px2 = bx + 0.5f * bw;
            const float py1 = by - 0.5f * bh, py2 = by + 0.5f * bh;
            const float t0  = 0.375f * (bw * bh);

            // silence test (same single-clamp arithmetic as hot role)
            float m = -1e30f;
            for (int n = lane; n < NBOX; n += 32) {
                const float4 g = s_box[n];
                float iw = fminf(px2, g.z) - fmaxf(px1, g.x);
                float ih = fminf(py2, g.w) - fmaxf(py1, g.y);
                m = fmaxf(m, sil_term(iw, ih, s_a375[n]));
            }
            m = warpReduceMax(m);
            const float mask_def = (m > t0) ? 0.0f : 1.0f;

            const float dx0 = sx - 0.5f, dy0 = sy - 0.5f;
            const float v_def = 0.5f * (dx0 * dx0 + dy0 * dy0 + q2 * q2 + q3 * q3 +
                                        cf * cf * mask_def);

            const float4 tb   = s_tbox[rid];
            const float  tcnf = s_iou[rid];
            const int    tc   = s_cls[rid];

            // 80-way log-softmax CE, lanes stride classes
            const float* cl = pb + 5 * HW;
            float mx = -1e30f;
            for (int c = lane; c < CC; c += 32) mx = fmaxf(mx, cl[c * HW]);
            mx = warpReduceMax(mx);
            float s = 0.0f;
            for (int c = lane; c < CC; c += 32) s += __expf(cl[c * HW] - mx);
            s = warpReduceSum(s);
            const float ce = mx + __logf(s) - cl[tc * HW];

            const float dx = sx - tb.x, dy = sy - tb.y;
            const float dw = q2 - tb.z, dh = q3 - tb.w;
            const float dc = cf - tcnf;
            const float v_true = 0.5f * (dx * dx + dy * dy + dw * dw + dh * dh +
                                         dc * dc * 5.0f) + ce;

            if (lane == 0) acc += v_true - v_def;
        }

        float wv = warpReduceSum(acc);
        if (lane == 0) s_red[warp] = wv;
        __syncthreads();
        if (warp == 0) {
            float bv = (lane < (BLK / 32)) ? s_red[lane] : 0.0f;
            bv = warpReduceSum(bv);
            if (lane == 0) atomicAdd(out, bv);
        }
        return;
    }

    // ===================== ROLE B: default-target loss =====================
    const int gid   = blockIdx.x - SCAT_BLOCKS;
    const int b     = gid / HOT_BLOCKS_PER_B;
    const int chunk = gid % HOT_BLOCKS_PER_B;

    if (tid < NBOX) {
        const float* t = target + (size_t)(b * NBOX + tid) * 5;
        float x = t[1] * WW, y = t[2] * HH, w = t[3] * WW, h = t[4] * HH;
        if (t[1] > 0.0f) {
            s_box[tid]  = make_float4(x - 0.5f * w, y - 0.5f * h,
                                      x + 0.5f * w, y + 0.5f * h);
            s_a375[tid] = 0.375f * (w * h);
        } else {
            s_box[tid]  = make_float4(1e30f, 1e30f, -1e30f, -1e30f);
            s_a375[tid] = 1e30f;
        }
    }
    __syncthreads();

    // two column-adjacent cells per thread (same row, same anchor plane)
    const int pi   = chunk * CELLS_PER_BLK + 2 * tid;
    const bool ok  = (pi + 1) < NCELL_PER_B;
    const int ci0  = ok ? pi : 0;

    const int a0 = ci0 / HW, r0 = ci0 % HW;
    const int col0 = r0 % WW;
    const int row0 = r0 / WW;

    const float* pb = pred + ((size_t)(b * AA + a0) * CH) * HW + r0;
    const float2 v0 = *(const float2*)(pb);
    const float2 v1 = *(const float2*)(pb + HW);
    const float2 v2 = *(const float2*)(pb + 2 * HW);
    const float2 v3 = *(const float2*)(pb + 3 * HW);
    const float2 v4 = *(const float2*)(pb + 4 * HW);

    const float sx0 = sigmoidf_(v0.x), sx1 = sigmoidf_(v0.y);
    const float sy0 = sigmoidf_(v1.x), sy1 = sigmoidf_(v1.y);
    const float cf0 = sigmoidf_(v4.x), cf1 = sigmoidf_(v4.y);

    const float bw0 = __expf(v2.x) * c_aw[a0], bh0 = __expf(v3.x) * c_ah[a0];
    const float bw1 = __expf(v2.y) * c_aw[a0], bh1 = __expf(v3.y) * c_ah[a0];

    const float bx0 = sx0 + (float)col0;
    const float bx1 = sx1 + (float)(col0 + 1);
    const float by0 = sy0 + (float)row0;
    const float by1 = sy1 + (float)row0;

    const float px1_0 = bx0 - 0.5f * bw0, px2_0 = bx0 + 0.5f * bw0;
    const float py1_0 = by0 - 0.5f * bh0, py2_0 = by0 + 0.5f * bh0;
    const float px1_1 = bx1 - 0.5f * bw1, px2_1 = bx1 + 0.5f * bw1;
    const float py1_1 = by1 - 0.5f * bh1, py2_1 = by1 + 0.5f * bh1;
    const float t0_0 = 0.375f * (bw0 * bh0);
    const float t0_1 = 0.375f * (bw1 * bh1);

    float m0 = -1e30f, m1 = -1e30f;
    #pragma unroll 10
    for (int n = 0; n < NBOX; n++) {
        const float4 g  = s_box[n];     // (x1, y1, x2, y2)
        const float  an = s_a375[n];

        float iw0 = fminf(px2_0, g.z) - fmaxf(px1_0, g.x);
        float ih0 = fminf(py2_0, g.w) - fmaxf(py1_0, g.y);
        m0 = fmaxf(m0, sil_term(iw0, ih0, an));

        float iw1 = fminf(px2_1, g.z) - fmaxf(px1_1, g.x);
        float ih1 = fminf(py2_1, g.w) - fmaxf(py1_1, g.y);
        m1 = fmaxf(m1, sil_term(iw1, ih1, an));
    }

    float v = 0.0f;
    if (ok) {
        const float mk0 = (m0 > t0_0) ? 0.0f : 1.0f;
        const float mk1 = (m1 > t0_1) ? 0.0f : 1.0f;
        const float dx0 = sx0 - 0.5f, dy0 = sy0 - 0.5f;
        const float dx1 = sx1 - 0.5f, dy1 = sy1 - 0.5f;
        v += 0.5f * (dx0 * dx0 + dy0 * dy0 + v2.x * v2.x + v3.x * v3.x +
                     cf0 * cf0 * mk0);
        v += 0.5f * (dx1 * dx1 + dy1 * dy1 + v2.y * v2.y + v3.y * v3.y +
                     cf1 * cf1 * mk1);
    }

    float wv = warpReduceSum(v);
    if (lane == 0) s_red[warp] = wv;
    __syncthreads();
    if (warp == 0) {
        float bv = (lane < (BLK / 32)) ? s_red[lane] : 0.0f;
        bv = warpReduceSum(bv);
        if (lane == 0) atomicAdd(out, bv);
    }
}

extern "C" void kernel_launch(void* const* d_in, const int* in_sizes, int n_in,
                              void* d_out, int out_size)
{
    const float* pred   = (const float*)d_in[0];
    const float* target = (const float*)d_in[1];
    float* out = (float*)d_out;

    cudaMemsetAsync(out, 0, (size_t)out_size * sizeof(float));
    region_loss_kernel<<<TOTAL_BLOCKS, BLK>>>(pred, target, out);
}